// round 2
// baseline (speedup 1.0000x reference)
#include <cuda_runtime.h>
#include <cstdint>

#define T_STEPS 256
#define H 512
#define W 512
#define HW (H * W)
#define TW 64
#define TH 16
#define SROWS 20          // TH + 4 halo rows
#define SCOLS 72          // TW + 8 (halo 2 each side, padded to 16B-aligned chunks)
#define NCHUNKS (SROWS * (SCOLS / 4))   // 360 float4 chunks per tile
#define NTHREADS 128

// ---- packed f32x2 helpers (ptxas never auto-fuses; PTX only) ----
__device__ __forceinline__ unsigned long long pk2(float lo, float hi) {
    unsigned long long r;
    asm("mov.b64 %0, {%1, %2};" : "=l"(r) : "f"(lo), "f"(hi));
    return r;
}
__device__ __forceinline__ void upk2(unsigned long long v, float& lo, float& hi) {
    asm("mov.b64 {%0, %1}, %2;" : "=f"(lo), "=f"(hi) : "l"(v));
}
__device__ __forceinline__ unsigned long long ffma2(unsigned long long a,
                                                    unsigned long long b,
                                                    unsigned long long c) {
    unsigned long long d;
    asm("fma.rn.f32x2 %0, %1, %2, %3;" : "=l"(d) : "l"(a), "l"(b), "l"(c));
    return d;
}

__device__ __forceinline__ void cp_async16(uint32_t smem_addr, const void* gptr) {
    asm volatile("cp.async.cg.shared.global [%0], [%1], 16;\n"
                 :: "r"(smem_addr), "l"(gptr));
}

__global__ __launch_bounds__(NTHREADS)
void snn_fused_kernel(const float* __restrict__ x,
                      const float* __restrict__ wk,
                      float* __restrict__ out)
{
    __shared__ float sb[2][SROWS][SCOLS];

    const int tid = threadIdx.x;
    const int tx = tid & 31;       // 0..31 -> 2-wide pair column
    const int ty = tid >> 5;       // 0..3  -> 4-tall row group
    const int tileX = blockIdx.x * TW;
    const int tileY = blockIdx.y * TH;

    // Zero both smem buffers once: out-of-range halo cells are never written
    // by cp.async, so they stay zero for all timesteps (SAME zero padding).
    for (int i = tid; i < 2 * SROWS * SCOLS; i += NTHREADS)
        ((float*)sb)[i] = 0.0f;

    // Pack conv weights as (w, w) pairs for f32x2.
    unsigned long long ww[25];
#pragma unroll
    for (int i = 0; i < 25; i++) {
        float w = __ldg(wk + i);
        ww[i] = pk2(w, w);
    }

    // Precompute this thread's <=3 cp.async chunks (t-invariant geometry).
    // Chunk k covers global row gy, cols [gx, gx+4). tileX-4 is 16B aligned,
    // so every chunk is either fully in-range or fully out.
    bool      cv[3];
    long long cg[3];
    uint32_t  cs[3];
#pragma unroll
    for (int k = 0; k < 3; k++) {
        int i  = tid + k * NTHREADS;
        int r  = i / (SCOLS / 4);
        int c4 = (i - r * (SCOLS / 4)) * 4;
        int gy = tileY - 2 + r;
        int gx = tileX - 4 + c4;
        cv[k] = (i < NCHUNKS) && (gy >= 0) && (gy < H) && (gx >= 0) && (gx + 4 <= W);
        cg[k] = (long long)gy * W + gx;
        cs[k] = (uint32_t)(r * SCOLS + c4) * 4u;
    }
    const uint32_t sbase = (uint32_t)__cvta_generic_to_shared(&sb[0][0][0]);
    const uint32_t bufbytes = SROWS * SCOLS * 4;

    __syncthreads();   // smem zeroing visible before first cp.async

    // Prefetch t = 0 into buffer 0.
    {
        const float* src = x;
#pragma unroll
        for (int k = 0; k < 3; k++)
            if (cv[k]) cp_async16(sbase + cs[k], src + cg[k]);
        asm volatile("cp.async.commit_group;\n");
    }

    // Per-pixel persistent state: 4 rows x 2 cols.
    float s1a[4], s1b[4], s2a[4], s2b[4];
#pragma unroll
    for (int r = 0; r < 4; r++) { s1a[r] = s1b[r] = s2a[r] = s2b[r] = 0.0f; }

    const int r0 = ty * 4;            // local output row base (0..12)
    const int cb = tx * 2 + 2;        // window start col in smem (even -> 8B aligned)
    float* outbase = out + (long long)(tileY + r0) * W + tileX + tx * 2;

    for (int t = 0; t < T_STEPS; t++) {
        const int cur = t & 1;
        const int nxt = cur ^ 1;

        if (t + 1 < T_STEPS) {
            const float* src = x + (long long)(t + 1) * HW;
            const uint32_t sb_n = sbase + (uint32_t)nxt * bufbytes;
#pragma unroll
            for (int k = 0; k < 3; k++)
                if (cv[k]) cp_async16(sb_n + cs[k], src + cg[k]);
            asm volatile("cp.async.commit_group;\n");
            asm volatile("cp.async.wait_group 1;\n");   // group(t) done, group(t+1) in flight
        } else {
            asm volatile("cp.async.wait_group 0;\n");
        }
        __syncthreads();

        // 5x5 conv, row-streaming over the 8-row window, f32x2 pairs.
        unsigned long long acc[4] = {0ull, 0ull, 0ull, 0ull};
#pragma unroll
        for (int rr = 0; rr < 8; rr++) {
            const float* rowp = &sb[cur][r0 + rr][cb];
            unsigned long long p0 = *(const unsigned long long*)(rowp);
            unsigned long long p1 = *(const unsigned long long*)(rowp + 2);
            unsigned long long p2 = *(const unsigned long long*)(rowp + 4);
            float f0, f1, f2, f3, f4, f5;
            upk2(p0, f0, f1); upk2(p1, f2, f3); upk2(p2, f4, f5);
            unsigned long long q1 = pk2(f1, f2);
            unsigned long long q3 = pk2(f3, f4);
            unsigned long long px[5] = {p0, q1, p1, q3, p2};
            const int olo = (rr > 4) ? rr - 4 : 0;
            const int ohi = (rr < 3) ? rr : 3;
#pragma unroll
            for (int o = olo; o <= ohi; o++) {
                const int ky = rr - o;
#pragma unroll
                for (int kx = 0; kx < 5; kx++)
                    acc[o] = ffma2(px[kx], ww[ky * 5 + kx], acc[o]);
            }
        }
        __syncthreads();   // all reads of sb[cur] done before next iter overwrites it

        // LIF (leak, fire, soft reset) + LI readout, store.
        float* orow = outbase + (long long)t * HW;
#pragma unroll
        for (int r = 0; r < 4; r++) {
            float c0, c1;
            upk2(acc[r], c0, c1);
            float v0 = fmaf(0.85f, s1a[r], c0);
            float v1 = fmaf(0.85f, s1b[r], c1);
            float k0 = (v0 >= 2.0f) ? 1.0f : 0.0f;
            float k1 = (v1 >= 2.0f) ? 1.0f : 0.0f;
            s1a[r] = fmaf(k0, -2.0f, v0);
            s1b[r] = fmaf(k1, -2.0f, v1);
            s2a[r] = fmaf(0.9f, s2a[r], k0);
            s2b[r] = fmaf(0.9f, s2b[r], k1);
            float2 o2 = make_float2(s2a[r], s2b[r]);
            *(float2*)(orow + (long long)r * W) = o2;
        }
    }
}

extern "C" void kernel_launch(void* const* d_in, const int* in_sizes, int n_in,
                              void* d_out, int out_size)
{
    const float* x  = (const float*)d_in[0];   // [256,1,512,512]
    const float* wk = (const float*)d_in[1];   // [1,1,5,5]
    float* out = (float*)d_out;                // [256,1,512,512]
    dim3 grid(W / TW, H / TH);                 // (8, 32) = 256 blocks
    snn_fused_kernel<<<grid, NTHREADS>>>(x, wk, out);
}

// round 3
// speedup vs baseline: 1.1425x; 1.1425x over previous
#include <cuda_runtime.h>
#include <cstdint>

#define T_STEPS 256
#define H 512
#define W 512
#define HW (H * W)
#define TW 64
#define TH 8
#define SROWS 12          // TH + 4 halo rows
#define SCOLS 72          // TW + 8 (halo, padded to 16B chunks)
#define NCHUNKS (SROWS * (SCOLS / 4))   // 216 float4 chunks per tile
#define NTHREADS 128
#define NBUF 3

// ---- packed f32x2 helpers (PTX only; ptxas never auto-fuses) ----
__device__ __forceinline__ unsigned long long pk2(float lo, float hi) {
    unsigned long long r;
    asm("mov.b64 %0, {%1, %2};" : "=l"(r) : "f"(lo), "f"(hi));
    return r;
}
__device__ __forceinline__ void upk2(unsigned long long v, float& lo, float& hi) {
    asm("mov.b64 {%0, %1}, %2;" : "=f"(lo), "=f"(hi) : "l"(v));
}
__device__ __forceinline__ unsigned long long ffma2(unsigned long long a,
                                                    unsigned long long b,
                                                    unsigned long long c) {
    unsigned long long d;
    asm("fma.rn.f32x2 %0, %1, %2, %3;" : "=l"(d) : "l"(a), "l"(b), "l"(c));
    return d;
}
__device__ __forceinline__ void cp_async16(uint32_t smem_addr, const void* gptr) {
    asm volatile("cp.async.cg.shared.global [%0], [%1], 16;\n"
                 :: "r"(smem_addr), "l"(gptr));
}

__global__ __launch_bounds__(NTHREADS)
void snn_fused_kernel(const float* __restrict__ x,
                      const float* __restrict__ wk,
                      float* __restrict__ out)
{
    __shared__ float sb[NBUF][SROWS][SCOLS];   // 3 * 12 * 72 * 4 = 10368 B

    const int tid = threadIdx.x;
    const int tx = tid & 31;       // 0..31 -> 2-wide pair column
    const int ty = tid >> 5;       // 0..3  -> 2-tall row pair
    const int tileX = blockIdx.x * TW;
    const int tileY = blockIdx.y * TH;

    // Zero all buffers once: out-of-range halo cells are never written by
    // cp.async, so they stay zero for all timesteps (SAME zero padding).
    for (int i = tid; i < NBUF * SROWS * SCOLS; i += NTHREADS)
        ((float*)sb)[i] = 0.0f;

    // Conv weights as (w, w) pairs for f32x2.
    unsigned long long ww[25];
#pragma unroll
    for (int i = 0; i < 25; i++) {
        float w = __ldg(wk + i);
        ww[i] = pk2(w, w);
    }

    // Per-thread cp.async chunk geometry (t-invariant). Chunk covers global
    // row gy, cols [gx, gx+4); all-in or all-out since everything is 16B tiled.
    bool      cv[2];
    long long cg[2];
    uint32_t  cs[2];
#pragma unroll
    for (int k = 0; k < 2; k++) {
        int i  = tid + k * NTHREADS;
        int r  = i / (SCOLS / 4);
        int c4 = (i - r * (SCOLS / 4)) * 4;
        int gy = tileY - 2 + r;
        int gx = tileX - 4 + c4;
        cv[k] = (i < NCHUNKS) && (gy >= 0) && (gy < H) && (gx >= 0) && (gx + 4 <= W);
        cg[k] = (long long)gy * W + gx;
        cs[k] = (uint32_t)(r * SCOLS + c4) * 4u;
    }
    const uint32_t sbase = (uint32_t)__cvta_generic_to_shared(&sb[0][0][0]);
    const uint32_t bufbytes = SROWS * SCOLS * 4;

    __syncthreads();   // smem zeroing visible before first cp.async

    // Prefetch t=0 -> B0 and t=1 -> B1 (two groups in flight).
#pragma unroll
    for (int p = 0; p < 2; p++) {
        const float* src = x + (long long)p * HW;
        const uint32_t sb_p = sbase + (uint32_t)p * bufbytes;
#pragma unroll
        for (int k = 0; k < 2; k++)
            if (cv[k]) cp_async16(sb_p + cs[k], src + cg[k]);
        asm volatile("cp.async.commit_group;\n");
    }

    // Persistent per-pixel state: 2 rows x 2 cols.
    float s1lo[2], s1hi[2], s2lo[2], s2hi[2];
#pragma unroll
    for (int r = 0; r < 2; r++) { s1lo[r] = s1hi[r] = s2lo[r] = s2hi[r] = 0.0f; }

    const int r0 = ty * 2;            // local output row base (0,2,4,6)
    const int cb = tx * 2 + 2;        // window start col in smem (8B aligned)
    float* outbase = out + (long long)(tileY + r0) * W + tileX + tx * 2;

#pragma unroll 1
    for (int t = 0; t < T_STEPS; t++) {
        const int buf = t % NBUF;

        // Group for t was issued 2 iters ago; force it complete (group t+1
        // stays in flight), then barrier for cross-thread visibility AND to
        // guarantee every warp is done reading B[(t-1)%3] before we overwrite
        // it below (it aliases B[(t+2)%3]).
        asm volatile("cp.async.wait_group 1;\n");
        __syncthreads();

        if (t + 2 < T_STEPS) {
            const float* src = x + (long long)(t + 2) * HW;
            const uint32_t sb_n = sbase + (uint32_t)((t + 2) % NBUF) * bufbytes;
#pragma unroll
            for (int k = 0; k < 2; k++)
                if (cv[k]) cp_async16(sb_n + cs[k], src + cg[k]);
        }
        asm volatile("cp.async.commit_group;\n");   // empty group ok at tail

        // 5x5 conv over a 6-row window, f32x2 pairs, 2 output rows.
        const float* bufbase = &sb[buf][0][0];
        unsigned long long acc0 = 0ull, acc1 = 0ull;
#pragma unroll
        for (int rr = 0; rr < 6; rr++) {
            const float* rowp = bufbase + (r0 + rr) * SCOLS + cb;
            unsigned long long p0 = *(const unsigned long long*)(rowp);
            unsigned long long p1 = *(const unsigned long long*)(rowp + 2);
            unsigned long long p2 = *(const unsigned long long*)(rowp + 4);
            float f0, f1, f2, f3, f4, f5;
            upk2(p0, f0, f1); upk2(p1, f2, f3); upk2(p2, f4, f5);
            unsigned long long px[5];
            px[0] = p0; px[1] = pk2(f1, f2); px[2] = p1; px[3] = pk2(f3, f4); px[4] = p2;
            if (rr < 5) {
#pragma unroll
                for (int kx = 0; kx < 5; kx++)
                    acc0 = ffma2(px[kx], ww[rr * 5 + kx], acc0);
            }
            if (rr >= 1) {
#pragma unroll
                for (int kx = 0; kx < 5; kx++)
                    acc1 = ffma2(px[kx], ww[(rr - 1) * 5 + kx], acc1);
            }
        }

        // LIF (leak, fire, soft reset) + LI readout, store.
        float* orow = outbase + (long long)t * HW;
        unsigned long long accs[2] = {acc0, acc1};
#pragma unroll
        for (int r = 0; r < 2; r++) {
            float c0, c1;
            upk2(accs[r], c0, c1);
            float v0 = fmaf(0.85f, s1lo[r], c0);
            float v1 = fmaf(0.85f, s1hi[r], c1);
            float k0 = (v0 >= 2.0f) ? 1.0f : 0.0f;
            float k1 = (v1 >= 2.0f) ? 1.0f : 0.0f;
            s1lo[r] = fmaf(k0, -2.0f, v0);
            s1hi[r] = fmaf(k1, -2.0f, v1);
            s2lo[r] = fmaf(0.9f, s2lo[r], k0);
            s2hi[r] = fmaf(0.9f, s2hi[r], k1);
            *(float2*)(orow + (long long)r * W) = make_float2(s2lo[r], s2hi[r]);
        }
    }
}

extern "C" void kernel_launch(void* const* d_in, const int* in_sizes, int n_in,
                              void* d_out, int out_size)
{
    const float* x  = (const float*)d_in[0];   // [256,1,512,512]
    const float* wk = (const float*)d_in[1];   // [1,1,5,5]
    float* out = (float*)d_out;                // [256,1,512,512]
    dim3 grid(W / TW, H / TH);                 // (8, 64) = 512 blocks
    snn_fused_kernel<<<grid, NTHREADS>>>(x, wk, out);
}